// round 8
// baseline (speedup 1.0000x reference)
#include <cuda_runtime.h>
#include <cuda_bf16.h>
#include <math.h>
#include <stdint.h>

#define T_   512
#define BB   64
#define HH   1024
#define N4   4096
#define RGRID 128   // blocks in persistent recurrence kernel

// ---------------- device scratch ----------------
__device__ float         g_zx[(size_t)T_ * BB * N4];        // x@Wi + b, fp32
__device__ __nv_bfloat16 g_xhi[(size_t)T_ * BB * HH];
__device__ __nv_bfloat16 g_xlo[(size_t)T_ * BB * HH];
__device__ __nv_bfloat16 g_WiT_hi[(size_t)N4 * HH];         // [n][k]
__device__ __nv_bfloat16 g_WiT_lo[(size_t)N4 * HH];
__device__ __nv_bfloat16 g_WhT_hi[(size_t)N4 * HH];         // [n][k] (pack source)
__device__ __nv_bfloat16 g_WhT_lo[(size_t)N4 * HH];

// Fragment-order operands for the recurrence MMA (no smem staging):
// A (h): [buf 2][m(4)][kc(64)][lane(32)] uint4
__device__ uint4 g_hfrag_hi[2][4 * 64 * 32];
__device__ uint4 g_hfrag_lo[2][4 * 64 * 32];
// B (Wh): [bid(128)][nhalf(2)][kc(64)][lane(32)] uint4
__device__ uint4 g_whfrag_hi[(size_t)128 * 2 * 64 * 32];
__device__ uint4 g_whfrag_lo[(size_t)128 * 2 * 64 * 32];

// ---------------- grid barrier ----------------
__device__ unsigned int          g_bar_count = 0;
__device__ volatile unsigned int g_bar_gen   = 0;

__device__ __forceinline__ void grid_barrier()
{
    __syncthreads();
    if (threadIdx.x == 0) {
        __threadfence();
        unsigned int gen = g_bar_gen;
        if (atomicAdd(&g_bar_count, 1) == RGRID - 1) {
            g_bar_count = 0;
            __threadfence();
            g_bar_gen = gen + 1;
        } else {
            while (g_bar_gen == gen) __nanosleep(32);
        }
        __threadfence();
    }
    __syncthreads();
}

// ---------------- helpers ----------------
__device__ __forceinline__ void bsplit(float v, __nv_bfloat16& hi, __nv_bfloat16& lo)
{
    hi = __float2bfloat16(v);
    lo = __float2bfloat16(v - __bfloat162float(hi));
}

__device__ __forceinline__ float fast_sigmoid(float x)
{
    return __frcp_rn(1.f + __expf(-x));
}
__device__ __forceinline__ float fast_tanh(float x)
{
    return 1.f - 2.f * __frcp_rn(__expf(2.f * x) + 1.f);
}

__device__ __forceinline__ void mma16816(float c[4],
                                         uint32_t a0, uint32_t a1, uint32_t a2, uint32_t a3,
                                         uint32_t b0, uint32_t b1)
{
    asm("mma.sync.aligned.m16n8k16.row.col.f32.bf16.bf16.f32 "
        "{%0,%1,%2,%3}, {%4,%5,%6,%7}, {%8,%9}, {%0,%1,%2,%3};"
        : "+f"(c[0]), "+f"(c[1]), "+f"(c[2]), "+f"(c[3])
        : "r"(a0), "r"(a1), "r"(a2), "r"(a3), "r"(b0), "r"(b1));
}

// ---------------------------------------------------------------------------
// Fused prep kernel (launch 1). Sections by blockIdx.x:
//  [0, 8192)        : split-convert x -> g_xhi/g_xlo  (4 float4 per thread)
//  [8192, 12288)    : transpose+split Wi -> g_WiT_hi/lo
//  [12288, 16384)   : transpose+split Wh -> g_WhT_hi/lo
//  [16384, 16512)   : h0 -> fragment buffer 0
// ---------------------------------------------------------------------------
__global__ __launch_bounds__(256) void prep_fused(const float* __restrict__ x,
                                                  const float* __restrict__ Wi,
                                                  const float* __restrict__ Wh,
                                                  const float* __restrict__ h0)
{
    const int blk = blockIdx.x;
    const int tid = threadIdx.x;

    if (blk < 8192) {
        const float4* xv = (const float4*)x;
        __nv_bfloat162* dh = reinterpret_cast<__nv_bfloat162*>(g_xhi);
        __nv_bfloat162* dl = reinterpret_cast<__nv_bfloat162*>(g_xlo);
#pragma unroll
        for (int j = 0; j < 4; j++) {
            int i = blk * 256 + tid + j * (8192 * 256);
            float4 v = xv[i];
            __nv_bfloat16 h0b,l0b,h1b,l1b,h2b,l2b,h3b,l3b;
            bsplit(v.x,h0b,l0b); bsplit(v.y,h1b,l1b);
            bsplit(v.z,h2b,l2b); bsplit(v.w,h3b,l3b);
            __nv_bfloat162 a; a.x=h0b; a.y=h1b; dh[2*i]   = a;
            __nv_bfloat162 b; b.x=h2b; b.y=h3b; dh[2*i+1] = b;
            __nv_bfloat162 c; c.x=l0b; c.y=l1b; dl[2*i]   = c;
            __nv_bfloat162 d; d.x=l2b; d.y=l3b; dl[2*i+1] = d;
        }
    } else if (blk < 16384) {
        __shared__ float tile[32][33];
        int which = (blk >= 12288);
        int tt = blk - (which ? 12288 : 8192);           // 0..4095
        const float* src = which ? Wh : Wi;
        int gx = (tt & 127) * 32;                        // n
        int gy = (tt >> 7) * 32;                         // k
#pragma unroll
        for (int i = 0; i < 4; i++) {
            int idx = tid + i * 256;
            int kl = idx >> 5, col = idx & 31;
            tile[kl][col] = src[(size_t)(gy + kl) * N4 + gx + col];
        }
        __syncthreads();
        __nv_bfloat16* dh = which ? g_WhT_hi : g_WiT_hi;
        __nv_bfloat16* dl = which ? g_WhT_lo : g_WiT_lo;
#pragma unroll
        for (int i = 0; i < 4; i++) {
            int idx = tid + i * 256;
            int nl = idx >> 5, kc = idx & 31;
            float v = tile[kc][nl];
            __nv_bfloat16 h, l; bsplit(v, h, l);
            dh[(size_t)(gx + nl) * HH + gy + kc] = h;
            dl[(size_t)(gx + nl) * HH + gy + kc] = l;
        }
    } else {
        int idx = (blk - 16384) * 256 + tid;             // 0 .. 64*512-1
        int b_ = idx >> 9;
        int p  = idx & 511;
        float v0 = h0[b_ * HH + 2 * p];
        float v1 = h0[b_ * HH + 2 * p + 1];
        __nv_bfloat16 h0b,l0b,h1b,l1b;
        bsplit(v0,h0b,l0b); bsplit(v1,h1b,l1b);
        __nv_bfloat162 wh; wh.x=h0b; wh.y=h1b;
        __nv_bfloat162 wl; wl.x=l0b; wl.y=l1b;

        int kc = p >> 3, within = p & 7;
        int tq = within & 3, whi = within >> 2;
        int m = b_ >> 4, r16 = b_ & 15;
        int gq = r16 & 7, top = r16 >> 3;
        int lane = gq * 4 + tq;
        int w = whi * 2 + top;
        uint32_t off = (uint32_t)(((m * 64 + kc) * 32 + lane) * 4 + w);
        ((uint32_t*)g_hfrag_hi[0])[off] = *(uint32_t*)&wh;
        ((uint32_t*)g_hfrag_lo[0])[off] = *(uint32_t*)&wl;
    }
}

// ---------------------------------------------------------------------------
// Launch 2 (fused): blocks [0,8192) = phase-1 GEMM tiles; [8192,10240) = Wh
// fragment pack (reads g_WhT written by launch 1).
// ---------------------------------------------------------------------------
__global__ __launch_bounds__(256) void gemm_wx_pack(const float* __restrict__ bias)
{
    const int blk = blockIdx.x;
    const int tid = threadIdx.x;

    if (blk >= 8192) {
        int widx = (blk - 8192) * 256 + tid;             // 0 .. 524287
        int lane  = widx & 31;
        int kc    = (widx >> 5) & 63;
        int nhalf = (widx >> 11) & 1;
        int bidn  = widx >> 12;
        int gq = lane >> 2, tq = lane & 3;

        const uint32_t* WH = (const uint32_t*)g_WhT_hi;  // [col][512 pairs]
        const uint32_t* WL = (const uint32_t*)g_WhT_lo;
        uint32_t hi[4], lo[4];
#pragma unroll
        for (int w = 0; w < 4; w++) {
            int j = w >> 1, b = w & 1;
            int zc = nhalf * 16 + j * 8 + gq;
            int col = (zc >> 3) * 1024 + bidn * 8 + (zc & 7);
            int pair = kc * 8 + tq + b * 4;
            hi[w] = WH[(size_t)col * 512 + pair];
            lo[w] = WL[(size_t)col * 512 + pair];
        }
        g_whfrag_hi[widx] = make_uint4(hi[0], hi[1], hi[2], hi[3]);
        g_whfrag_lo[widx] = make_uint4(lo[0], lo[1], lo[2], lo[3]);
        return;
    }

    // ---- phase-1 GEMM: 128x128 tile, 8 warps, warp 64x32, kt=32 ----
    __shared__ uint32_t sAh[128 * 20], sAl[128 * 20];
    __shared__ uint32_t sBh[128 * 20], sBl[128 * 20];

    const uint32_t* Xh = (const uint32_t*)g_xhi;
    const uint32_t* Xl = (const uint32_t*)g_xlo;
    const uint32_t* Wh = (const uint32_t*)g_WiT_hi;
    const uint32_t* Wl = (const uint32_t*)g_WiT_lo;

    const int bn   = (blk & 31) * 128;
    const int bm   = (blk >> 5) * 128;
    const int lane = tid & 31, wp = tid >> 5;
    const int g    = lane >> 2, tq = lane & 3;
    const int wm   = (wp >> 2) * 64;
    const int wn   = (wp & 3) * 32;
    const int r0   = wp * 2 + (lane >> 4);
    const int kw   = lane & 15;

    float acc[4][4][4] = {};
    uint32_t pAh[8], pAl[8], pBh[8], pBl[8];

    auto LOAD = [&](int kc) {
        int k0w = kc * 16;
#pragma unroll
        for (int i = 0; i < 8; i++) {
            int row = r0 + 16 * i;
            size_t ga = (size_t)(bm + row) * 512 + k0w + kw;
            size_t gb = (size_t)(bn + row) * 512 + k0w + kw;
            pAh[i] = Xh[ga]; pAl[i] = Xl[ga];
            pBh[i] = Wh[gb]; pBl[i] = Wl[gb];
        }
    };
    auto STORE = [&]() {
#pragma unroll
        for (int i = 0; i < 8; i++) {
            int row = r0 + 16 * i;
            sAh[row * 20 + kw] = pAh[i]; sAl[row * 20 + kw] = pAl[i];
            sBh[row * 20 + kw] = pBh[i]; sBl[row * 20 + kw] = pBl[i];
        }
    };

    LOAD(0); STORE(); __syncthreads();

    for (int kc = 0; kc < 32; kc++) {
        if (kc < 31) LOAD(kc + 1);
#pragma unroll
        for (int s = 0; s < 2; s++) {
            int kwb = s * 8;
            uint32_t bh[4][2], bl[4][2];
#pragma unroll
            for (int nf = 0; nf < 4; nf++) {
                int base = (wn + nf * 8 + g) * 20 + kwb + tq;
                bh[nf][0] = sBh[base]; bh[nf][1] = sBh[base + 4];
                bl[nf][0] = sBl[base]; bl[nf][1] = sBl[base + 4];
            }
#pragma unroll
            for (int mf = 0; mf < 4; mf++) {
                int rb = (wm + mf * 16 + g) * 20 + kwb + tq;
                uint32_t a0 = sAh[rb], a1 = sAh[rb + 160];
                uint32_t a2 = sAh[rb + 4], a3 = sAh[rb + 164];
                uint32_t l0 = sAl[rb], l1 = sAl[rb + 160];
                uint32_t l2 = sAl[rb + 4], l3 = sAl[rb + 164];
#pragma unroll
                for (int nf = 0; nf < 4; nf++) {
                    mma16816(acc[mf][nf], a0, a1, a2, a3, bh[nf][0], bh[nf][1]);
                    mma16816(acc[mf][nf], a0, a1, a2, a3, bl[nf][0], bl[nf][1]);
                    mma16816(acc[mf][nf], l0, l1, l2, l3, bh[nf][0], bh[nf][1]);
                }
            }
        }
        __syncthreads();
        if (kc < 31) { STORE(); __syncthreads(); }
    }

#pragma unroll
    for (int mf = 0; mf < 4; mf++) {
        int row0 = bm + wm + mf * 16 + g;
#pragma unroll
        for (int nf = 0; nf < 4; nf++) {
            int col = bn + wn + nf * 8 + tq * 2;
            float2 bb = *(const float2*)&bias[col];
            float2 v0, v1;
            v0.x = acc[mf][nf][0] + bb.x; v0.y = acc[mf][nf][1] + bb.y;
            v1.x = acc[mf][nf][2] + bb.x; v1.y = acc[mf][nf][3] + bb.y;
            *(float2*)&g_zx[(size_t)row0 * N4 + col]       = v0;
            *(float2*)&g_zx[(size_t)(row0 + 8) * N4 + col] = v1;
        }
    }
}

// ---------------------------------------------------------------------------
// Persistent recurrence (launch 3): 128 blocks x 256 thr.
// New tiling: each warp computes the FULL m64 x n32 tile over a disjoint K/8
// slice (8 k16 chunks) -> no duplicated operand reads within the block.
// Partials combined via a 3-stage smem reduction tree (deterministic).
// ---------------------------------------------------------------------------
__global__ __launch_bounds__(256, 1)
void lstm_rec_mma(const float* __restrict__ c0,
                  float* __restrict__ ys,
                  float* __restrict__ cT,
                  float* __restrict__ hT)
{
    __shared__ float Zpart[4][2048];   // 32 KB staged reduction
    __shared__ float Z[64][33];        // final z tile for pointwise gather

    const int tid  = threadIdx.x, bid = blockIdx.x;
    const int lane = tid & 31, wp = tid >> 5;
    const int gq   = lane >> 2, tq = lane & 3;
    const int jb   = bid * 8;
    const int kbase = wp * 8;          // this warp's K-chunk slice [kbase, kbase+8)

    const uint4* WBh0 = g_whfrag_hi + ((size_t)(bid * 2 + 0) * 64) * 32;
    const uint4* WBl0 = g_whfrag_lo + ((size_t)(bid * 2 + 0) * 64) * 32;
    const uint4* WBh1 = g_whfrag_hi + ((size_t)(bid * 2 + 1) * 64) * 32;
    const uint4* WBl1 = g_whfrag_lo + ((size_t)(bid * 2 + 1) * 64) * 32;

    // pointwise decode
    const int pb  = tid >> 2;
    const int jj  = (tid & 3) * 2;
    const int j0  = jb + jj;
    const int p_g   = j0 >> 1;
    const int kcw   = p_g >> 3, within = p_g & 7;
    const int ptq   = within & 3, pwhi = within >> 2;
    const int pm    = pb >> 4, r16 = pb & 15;
    const int pg    = r16 & 7, ptop = r16 >> 3;
    const uint32_t hoff = (uint32_t)((((pm * 64 + kcw) * 32) + pg * 4 + ptq) * 4
                                     + pwhi * 2 + ptop);

    for (int t = 0; t < T_; t++) {
        const uint4* AH = g_hfrag_hi[t & 1];
        const uint4* AL = g_hfrag_lo[t & 1];

        // ---- prefetch pointwise operands (DRAM latency overlaps k-loop) ----
        const float* zx = g_zx + (size_t)t * BB * N4 + (size_t)pb * N4;
        const float* cp = (t == 0) ? c0 : cT;
        float2 xi = *(const float2*)&zx[j0];
        float2 xf = *(const float2*)&zx[HH + j0];
        float2 xg = *(const float2*)&zx[2 * HH + j0];
        float2 xo = *(const float2*)&zx[3 * HH + j0];
        float2 cv = *(const float2*)&cp[(size_t)pb * HH + j0];

        float acc[4][4][4];
#pragma unroll
        for (int a = 0; a < 4; a++)
#pragma unroll
            for (int b = 0; b < 4; b++)
#pragma unroll
                for (int r = 0; r < 4; r++) acc[a][b][r] = 0.f;

        uint4 bAh[2][4], bAl[2][4], bBh[2][2], bBl[2][2];

        // prologue: chunk 0 of this warp's slice
        {
            int off = kbase * 32 + lane;
#pragma unroll
            for (int m = 0; m < 4; m++) {
                bAh[0][m] = AH[m * 2048 + off];
                bAl[0][m] = AL[m * 2048 + off];
            }
            bBh[0][0] = WBh0[off]; bBh[0][1] = WBh1[off];
            bBl[0][0] = WBl0[off]; bBl[0][1] = WBl1[off];
        }

#pragma unroll
        for (int i = 0; i < 8; i++) {
            int cur = i & 1, nxt = cur ^ 1;
            if (i < 7) {
                int off = (kbase + i + 1) * 32 + lane;
#pragma unroll
                for (int m = 0; m < 4; m++) {
                    bAh[nxt][m] = AH[m * 2048 + off];
                    bAl[nxt][m] = AL[m * 2048 + off];
                }
                bBh[nxt][0] = WBh0[off]; bBh[nxt][1] = WBh1[off];
                bBl[nxt][0] = WBl0[off]; bBl[nxt][1] = WBl1[off];
            }
            uint4 b0h = bBh[cur][0], b0l = bBl[cur][0];
            uint4 b1h = bBh[cur][1], b1l = bBl[cur][1];
#pragma unroll
            for (int m = 0; m < 4; m++) {
                uint4 ah = bAh[cur][m], al = bAl[cur][m];
                // nf0 = (nhalf0, j0), nf1 = (nhalf0, j1)
                mma16816(acc[m][0], ah.x, ah.y, ah.z, ah.w, b0h.x, b0h.y);
                mma16816(acc[m][0], ah.x, ah.y, ah.z, ah.w, b0l.x, b0l.y);
                mma16816(acc[m][0], al.x, al.y, al.z, al.w, b0h.x, b0h.y);
                mma16816(acc[m][1], ah.x, ah.y, ah.z, ah.w, b0h.z, b0h.w);
                mma16816(acc[m][1], ah.x, ah.y, ah.z, ah.w, b0l.z, b0l.w);
                mma16816(acc[m][1], al.x, al.y, al.z, al.w, b0h.z, b0h.w);
                // nf2 = (nhalf1, j0), nf3 = (nhalf1, j1)
                mma16816(acc[m][2], ah.x, ah.y, ah.z, ah.w, b1h.x, b1h.y);
                mma16816(acc[m][2], ah.x, ah.y, ah.z, ah.w, b1l.x, b1l.y);
                mma16816(acc[m][2], al.x, al.y, al.z, al.w, b1h.x, b1h.y);
                mma16816(acc[m][3], ah.x, ah.y, ah.z, ah.w, b1h.z, b1h.w);
                mma16816(acc[m][3], ah.x, ah.y, ah.z, ah.w, b1l.z, b1l.w);
                mma16816(acc[m][3], al.x, al.y, al.z, al.w, b1h.z, b1h.w);
            }
        }

        // ---- staged K-split reduction (8 -> 4 -> 2 -> 1 partials) ----
        if (wp >= 4) {
            int w = wp - 4;
#pragma unroll
            for (int mf = 0; mf < 4; mf++)
#pragma unroll
                for (int nf = 0; nf < 4; nf++)
#pragma unroll
                    for (int r = 0; r < 4; r++)
                        Zpart[w][(((mf * 4 + nf) * 4) + r) * 32 + lane] = acc[mf][nf][r];
        }
        __syncthreads();
        if (wp < 4) {
#pragma unroll
            for (int mf = 0; mf < 4; mf++)
#pragma unroll
                for (int nf = 0; nf < 4; nf++)
#pragma unroll
                    for (int r = 0; r < 4; r++)
                        acc[mf][nf][r] += Zpart[wp][(((mf * 4 + nf) * 4) + r) * 32 + lane];
        }
        __syncthreads();
        if (wp == 2 || wp == 3) {
            int w = wp - 2;
#pragma unroll
            for (int mf = 0; mf < 4; mf++)
#pragma unroll
                for (int nf = 0; nf < 4; nf++)
#pragma unroll
                    for (int r = 0; r < 4; r++)
                        Zpart[w][(((mf * 4 + nf) * 4) + r) * 32 + lane] = acc[mf][nf][r];
        }
        __syncthreads();
        if (wp < 2) {
#pragma unroll
            for (int mf = 0; mf < 4; mf++)
#pragma unroll
                for (int nf = 0; nf < 4; nf++)
#pragma unroll
                    for (int r = 0; r < 4; r++)
                        acc[mf][nf][r] += Zpart[wp][(((mf * 4 + nf) * 4) + r) * 32 + lane];
        }
        __syncthreads();
        if (wp == 1) {
#pragma unroll
            for (int mf = 0; mf < 4; mf++)
#pragma unroll
                for (int nf = 0; nf < 4; nf++)
#pragma unroll
                    for (int r = 0; r < 4; r++)
                        Zpart[0][(((mf * 4 + nf) * 4) + r) * 32 + lane] = acc[mf][nf][r];
        }
        __syncthreads();
        if (wp == 0) {
#pragma unroll
            for (int mf = 0; mf < 4; mf++) {
#pragma unroll
                for (int nf = 0; nf < 4; nf++) {
#pragma unroll
                    for (int r = 0; r < 4; r++)
                        acc[mf][nf][r] += Zpart[0][(((mf * 4 + nf) * 4) + r) * 32 + lane];
                    int zb = (nf >> 1) * 16 + (nf & 1) * 8 + tq * 2;
                    int row = mf * 16 + gq;
                    Z[row][zb]         = acc[mf][nf][0];
                    Z[row][zb + 1]     = acc[mf][nf][1];
                    Z[row + 8][zb]     = acc[mf][nf][2];
                    Z[row + 8][zb + 1] = acc[mf][nf][3];
                }
            }
        }
        __syncthreads();

        // ---- pointwise gates ----
        {
            float* ys_t = ys + (size_t)t * BB * HH;
            uint32_t* nhh = (uint32_t*)g_hfrag_hi[(t + 1) & 1];
            uint32_t* nhl = (uint32_t*)g_hfrag_lo[(t + 1) & 1];

            float h2[2], c2[2];
#pragma unroll
            for (int e = 0; e < 2; e++) {
                int zc = jj + e;
                float zi = Z[pb][zc]      + (e ? xi.y : xi.x);
                float zf = Z[pb][8 + zc]  + (e ? xf.y : xf.x);
                float zg = Z[pb][16 + zc] + (e ? xg.y : xg.x);
                float zo = Z[pb][24 + zc] + (e ? xo.y : xo.x);

                float ig = fast_sigmoid(zi);
                float fg = fast_sigmoid(zf);
                float gg = fast_tanh(zg);
                float og = fast_sigmoid(zo);

                float cc = fg * (e ? cv.y : cv.x) + ig * gg;
                c2[e] = cc;
                h2[e] = og * fast_tanh(cc);
            }

            *(float2*)&cT[(size_t)pb * HH + j0]   = *(float2*)c2;
            *(float2*)&ys_t[(size_t)pb * HH + j0] = *(float2*)h2;
            if (t == T_ - 1) *(float2*)&hT[(size_t)pb * HH + j0] = *(float2*)h2;

            __nv_bfloat16 h0b,l0b,h1b,l1b;
            bsplit(h2[0], h0b, l0b); bsplit(h2[1], h1b, l1b);
            __nv_bfloat162 wh; wh.x = h0b; wh.y = h1b;
            __nv_bfloat162 wl; wl.x = l0b; wl.y = l1b;
            nhh[hoff] = *(uint32_t*)&wh;
            nhl[hoff] = *(uint32_t*)&wl;
        }

        grid_barrier();
    }
}

// ---------------------------------------------------------------------------
extern "C" void kernel_launch(void* const* d_in, const int* in_sizes, int n_in,
                              void* d_out, int out_size)
{
    const float* x  = (const float*)d_in[0];   // [T,B,D]
    const float* c0 = (const float*)d_in[1];   // [B,H]
    const float* h0 = (const float*)d_in[2];   // [B,H]
    const float* Wi = (const float*)d_in[3];   // [D,4H]
    const float* Wh = (const float*)d_in[4];   // [H,4H]
    const float* b  = (const float*)d_in[5];   // [4H]

    float* out = (float*)d_out;
    float* ys = out;                                  // [T,B,H]
    float* cT = out + (size_t)T_ * BB * HH;           // [B,H]
    float* hT = cT + (size_t)BB * HH;                 // [B,H]

    prep_fused<<<16512, 256>>>(x, Wi, Wh, h0);        // launch 1
    gemm_wx_pack<<<10240, 256>>>(b);                  // launch 2
    lstm_rec_mma<<<RGRID, 256>>>(c0, ys, cT, hT);     // launch 3
}